// round 1
// baseline (speedup 1.0000x reference)
#include <cuda_runtime.h>
#include <cuda_bf16.h>
#include <cstdint>
#include <cstddef>

// Problem constants
#define T_TOK 2048      // B*S = 4*512 tokens
#define D_DIM 512
#define H_DIM 2048
#define N_EXP 8
#define BM 128
#define BN 128
#define BK 32
#define PAD_ROWS 3072   // 2048 + 8*128 worst-case padding
#define MAX_TILES 24    // floor(2048/128) + 8
#define AS_STRIDE 36    // 128x(32+4) fp32/tf32 words, conflict-free frag reads
#define BS_STRIDE 136   // 32x(128+8)

// Scratch (allocation-free rule: device globals)
__device__ int   g_perm[PAD_ROWS];
__device__ int   g_tile_expert[MAX_TILES + 8];
__device__ float g_h[(size_t)PAD_ROWS * H_DIM];     // fp32 intermediate (precision)
__device__ float g_ffn[(size_t)T_TOK * D_DIM];

__device__ __forceinline__ uint32_t f2tf(float f) {
    uint32_t r;
    asm("cvt.rna.tf32.f32 %0, %1;" : "=r"(r) : "f"(f));
    return r;
}

__device__ __forceinline__ void mma8(float* c,
                                     uint32_t a0, uint32_t a1, uint32_t a2, uint32_t a3,
                                     uint32_t b0, uint32_t b1) {
    asm volatile(
        "mma.sync.aligned.m16n8k8.row.col.f32.tf32.tf32.f32 "
        "{%0,%1,%2,%3}, {%4,%5,%6,%7}, {%8,%9}, {%0,%1,%2,%3};\n"
        : "+f"(c[0]), "+f"(c[1]), "+f"(c[2]), "+f"(c[3])
        : "r"(a0), "r"(a1), "r"(a2), "r"(a3), "r"(b0), "r"(b1));
}

// ---------------------------------------------------------------------------
// Setup: bins -> histogram -> padded grouped permutation + tile expert table
// ---------------------------------------------------------------------------
__global__ void setup_kernel(const int* __restrict__ orig, const int* __restrict__ hmap) {
    __shared__ int cnt[N_EXP];
    __shared__ int padoff[N_EXP];
    __shared__ int scat[N_EXP];
    int tid = threadIdx.x;

    if (tid < N_EXP) cnt[tid] = 0;
    __syncthreads();

    for (int t = tid; t < T_TOK; t += 256) {
        int b = hmap[orig[t]];
        atomicAdd(&cnt[b], 1);
    }
    for (int i = tid; i < PAD_ROWS; i += 256) g_perm[i] = -1;
    if (tid < MAX_TILES + 8) g_tile_expert[tid] = -1;
    __syncthreads();

    if (tid == 0) {
        int tile = 0;
        for (int e = 0; e < N_EXP; e++) {
            padoff[e] = tile * BM;
            scat[e] = 0;
            int nt = (cnt[e] + BM - 1) / BM;
            for (int i = 0; i < nt; i++) g_tile_expert[tile++] = e;
        }
    }
    __syncthreads();

    for (int t = tid; t < T_TOK; t += 256) {
        int b = hmap[orig[t]];
        int r = atomicAdd(&scat[b], 1);
        g_perm[padoff[b] + r] = t;
    }
}

// ---------------------------------------------------------------------------
// GEMM1: h = relu(x[perm] @ W1[e] + b1[e])   (tf32 mma, 128x128x32 tiles)
// grid = (MAX_TILES, H/128), 256 threads, warps 2(M) x 4(N), warp tile 64x32
// ---------------------------------------------------------------------------
__global__ __launch_bounds__(256, 2) void gemm1_kernel(const float* __restrict__ x,
                                                       const float* __restrict__ W1,
                                                       const float* __restrict__ b1) {
    int te = g_tile_expert[blockIdx.x];
    if (te < 0) return;

    __shared__ uint32_t As[BM * AS_STRIDE];
    __shared__ uint32_t Bs[BK * BS_STRIDE];
    __shared__ int toks[BM];

    int tid = threadIdx.x;
    if (tid < BM) toks[tid] = g_perm[blockIdx.x * BM + tid];
    __syncthreads();

    const float* We = W1 + (size_t)te * D_DIM * H_DIM;
    int nbase = blockIdx.y * BN;
    int lane = tid & 31, wid = tid >> 5;
    int wm = wid & 1, wn = wid >> 1;
    int gid = lane >> 2, tig = lane & 3;

    float acc[4][4][4];
#pragma unroll
    for (int i = 0; i < 4; i++)
#pragma unroll
        for (int j = 0; j < 4; j++)
#pragma unroll
            for (int k = 0; k < 4; k++) acc[i][j][k] = 0.f;

    for (int kb = 0; kb < D_DIM / BK; ++kb) {
        float4 av[4], bv[4];
#pragma unroll
        for (int j = 0; j < 4; ++j) {
            int l = tid + 256 * j;
            int r = l >> 3, c4 = l & 7;
            int tk = toks[r];
            float4 v = make_float4(0.f, 0.f, 0.f, 0.f);
            if (tk >= 0) v = *(const float4*)(x + (size_t)tk * D_DIM + kb * BK + c4 * 4);
            av[j] = v;
        }
#pragma unroll
        for (int j = 0; j < 4; ++j) {
            int l = tid + 256 * j;
            int r = l >> 5, c4 = l & 31;
            bv[j] = *(const float4*)(We + (size_t)(kb * BK + r) * H_DIM + nbase + c4 * 4);
        }
        __syncthreads();
#pragma unroll
        for (int j = 0; j < 4; ++j) {
            int l = tid + 256 * j;
            int r = l >> 3, c4 = l & 7;
            uint32_t* p = &As[r * AS_STRIDE + c4 * 4];
            p[0] = f2tf(av[j].x); p[1] = f2tf(av[j].y);
            p[2] = f2tf(av[j].z); p[3] = f2tf(av[j].w);
        }
#pragma unroll
        for (int j = 0; j < 4; ++j) {
            int l = tid + 256 * j;
            int r = l >> 5, c4 = l & 31;
            uint32_t* p = &Bs[r * BS_STRIDE + c4 * 4];
            p[0] = f2tf(bv[j].x); p[1] = f2tf(bv[j].y);
            p[2] = f2tf(bv[j].z); p[3] = f2tf(bv[j].w);
        }
        __syncthreads();

#pragma unroll
        for (int ks = 0; ks < 4; ++ks) {
            int k0 = ks * 8;
            uint32_t af[4][4], bf[4][2];
#pragma unroll
            for (int mi = 0; mi < 4; ++mi) {
                int r0 = wm * 64 + mi * 16 + gid;
                af[mi][0] = As[r0 * AS_STRIDE + k0 + tig];
                af[mi][1] = As[(r0 + 8) * AS_STRIDE + k0 + tig];
                af[mi][2] = As[r0 * AS_STRIDE + k0 + tig + 4];
                af[mi][3] = As[(r0 + 8) * AS_STRIDE + k0 + tig + 4];
            }
#pragma unroll
            for (int ni = 0; ni < 4; ++ni) {
                int cb = wn * 32 + ni * 8 + gid;
                bf[ni][0] = Bs[(k0 + tig) * BS_STRIDE + cb];
                bf[ni][1] = Bs[(k0 + tig + 4) * BS_STRIDE + cb];
            }
#pragma unroll
            for (int mi = 0; mi < 4; ++mi)
#pragma unroll
                for (int ni = 0; ni < 4; ++ni)
                    mma8(acc[mi][ni], af[mi][0], af[mi][1], af[mi][2], af[mi][3],
                         bf[ni][0], bf[ni][1]);
        }
        __syncthreads();
    }

    // Epilogue: + bias, ReLU, store fp32 h (padding rows get harmless values)
    const float* be = b1 + (size_t)te * H_DIM;
    int rowbase = blockIdx.x * BM;
#pragma unroll
    for (int ni = 0; ni < 4; ++ni) {
        int c0 = nbase + wn * 32 + ni * 8 + tig * 2;
        float bb0 = be[c0], bb1 = be[c0 + 1];
#pragma unroll
        for (int mi = 0; mi < 4; ++mi) {
            int r0 = rowbase + wm * 64 + mi * 16 + gid;
            float2 v0, v1;
            v0.x = fmaxf(acc[mi][ni][0] + bb0, 0.f);
            v0.y = fmaxf(acc[mi][ni][1] + bb1, 0.f);
            v1.x = fmaxf(acc[mi][ni][2] + bb0, 0.f);
            v1.y = fmaxf(acc[mi][ni][3] + bb1, 0.f);
            *(float2*)(g_h + (size_t)r0 * H_DIM + c0) = v0;
            *(float2*)(g_h + (size_t)(r0 + 8) * H_DIM + c0) = v1;
        }
    }
}

// ---------------------------------------------------------------------------
// GEMM2: y = h @ W2[e] + b2[e], scatter to g_ffn[token]
// grid = (MAX_TILES, D/128)
// ---------------------------------------------------------------------------
__global__ __launch_bounds__(256, 2) void gemm2_kernel(const float* __restrict__ W2,
                                                       const float* __restrict__ b2) {
    int te = g_tile_expert[blockIdx.x];
    if (te < 0) return;

    __shared__ uint32_t As[BM * AS_STRIDE];
    __shared__ uint32_t Bs[BK * BS_STRIDE];
    __shared__ int toks[BM];

    int tid = threadIdx.x;
    if (tid < BM) toks[tid] = g_perm[blockIdx.x * BM + tid];
    __syncthreads();

    const float* We = W2 + (size_t)te * H_DIM * D_DIM;
    const float* Ae = g_h + (size_t)blockIdx.x * BM * H_DIM;
    int nbase = blockIdx.y * BN;
    int lane = tid & 31, wid = tid >> 5;
    int wm = wid & 1, wn = wid >> 1;
    int gid = lane >> 2, tig = lane & 3;

    float acc[4][4][4];
#pragma unroll
    for (int i = 0; i < 4; i++)
#pragma unroll
        for (int j = 0; j < 4; j++)
#pragma unroll
            for (int k = 0; k < 4; k++) acc[i][j][k] = 0.f;

    for (int kb = 0; kb < H_DIM / BK; ++kb) {
        float4 av[4], bv[4];
#pragma unroll
        for (int j = 0; j < 4; ++j) {
            int l = tid + 256 * j;
            int r = l >> 3, c4 = l & 7;
            av[j] = *(const float4*)(Ae + (size_t)r * H_DIM + kb * BK + c4 * 4);
        }
#pragma unroll
        for (int j = 0; j < 4; ++j) {
            int l = tid + 256 * j;
            int r = l >> 5, c4 = l & 31;
            bv[j] = *(const float4*)(We + (size_t)(kb * BK + r) * D_DIM + nbase + c4 * 4);
        }
        __syncthreads();
#pragma unroll
        for (int j = 0; j < 4; ++j) {
            int l = tid + 256 * j;
            int r = l >> 3, c4 = l & 7;
            uint32_t* p = &As[r * AS_STRIDE + c4 * 4];
            p[0] = f2tf(av[j].x); p[1] = f2tf(av[j].y);
            p[2] = f2tf(av[j].z); p[3] = f2tf(av[j].w);
        }
#pragma unroll
        for (int j = 0; j < 4; ++j) {
            int l = tid + 256 * j;
            int r = l >> 5, c4 = l & 31;
            uint32_t* p = &Bs[r * BS_STRIDE + c4 * 4];
            p[0] = f2tf(bv[j].x); p[1] = f2tf(bv[j].y);
            p[2] = f2tf(bv[j].z); p[3] = f2tf(bv[j].w);
        }
        __syncthreads();

#pragma unroll
        for (int ks = 0; ks < 4; ++ks) {
            int k0 = ks * 8;
            uint32_t af[4][4], bf[4][2];
#pragma unroll
            for (int mi = 0; mi < 4; ++mi) {
                int r0 = wm * 64 + mi * 16 + gid;
                af[mi][0] = As[r0 * AS_STRIDE + k0 + tig];
                af[mi][1] = As[(r0 + 8) * AS_STRIDE + k0 + tig];
                af[mi][2] = As[r0 * AS_STRIDE + k0 + tig + 4];
                af[mi][3] = As[(r0 + 8) * AS_STRIDE + k0 + tig + 4];
            }
#pragma unroll
            for (int ni = 0; ni < 4; ++ni) {
                int cb = wn * 32 + ni * 8 + gid;
                bf[ni][0] = Bs[(k0 + tig) * BS_STRIDE + cb];
                bf[ni][1] = Bs[(k0 + tig + 4) * BS_STRIDE + cb];
            }
#pragma unroll
            for (int mi = 0; mi < 4; ++mi)
#pragma unroll
                for (int ni = 0; ni < 4; ++ni)
                    mma8(acc[mi][ni], af[mi][0], af[mi][1], af[mi][2], af[mi][3],
                         bf[ni][0], bf[ni][1]);
        }
        __syncthreads();
    }

    const float* be = b2 + (size_t)te * D_DIM;
#pragma unroll
    for (int ni = 0; ni < 4; ++ni) {
        int c0 = nbase + wn * 32 + ni * 8 + tig * 2;
        float bb0 = be[c0], bb1 = be[c0 + 1];
#pragma unroll
        for (int mi = 0; mi < 4; ++mi) {
            int rl0 = wm * 64 + mi * 16 + gid;
            int tk0 = toks[rl0];
            int tk1 = toks[rl0 + 8];
            if (tk0 >= 0) {
                float2 v;
                v.x = acc[mi][ni][0] + bb0;
                v.y = acc[mi][ni][1] + bb1;
                *(float2*)(g_ffn + (size_t)tk0 * D_DIM + c0) = v;
            }
            if (tk1 >= 0) {
                float2 v;
                v.x = acc[mi][ni][2] + bb0;
                v.y = acc[mi][ni][3] + bb1;
                *(float2*)(g_ffn + (size_t)tk1 * D_DIM + c0) = v;
            }
        }
    }
}

// ---------------------------------------------------------------------------
// Residual + LayerNorm: out = LN(x + ffn) * gamma + beta
// ---------------------------------------------------------------------------
__global__ void ln_kernel(const float* __restrict__ x,
                          const float* __restrict__ gamma,
                          const float* __restrict__ beta,
                          float* __restrict__ out) {
    int t = blockIdx.x;
    int tid = threadIdx.x;  // 128
    const float* xr = x + (size_t)t * D_DIM;
    const float* fr = g_ffn + (size_t)t * D_DIM;

    float v[4];
    float s = 0.f, ss = 0.f;
#pragma unroll
    for (int i = 0; i < 4; i++) {
        int c = tid + i * 128;
        float z = xr[c] + fr[c];
        v[i] = z;
        s += z;
        ss += z * z;
    }
#pragma unroll
    for (int o = 16; o > 0; o >>= 1) {
        s += __shfl_xor_sync(0xffffffffu, s, o);
        ss += __shfl_xor_sync(0xffffffffu, ss, o);
    }
    __shared__ float sm[8];
    int w = tid >> 5;
    if ((tid & 31) == 0) { sm[w] = s; sm[4 + w] = ss; }
    __syncthreads();
    s = sm[0] + sm[1] + sm[2] + sm[3];
    ss = sm[4] + sm[5] + sm[6] + sm[7];

    float mean = s * (1.f / 512.f);
    float var = ss * (1.f / 512.f) - mean * mean;
    float rstd = rsqrtf(var + 1e-5f);
#pragma unroll
    for (int i = 0; i < 4; i++) {
        int c = tid + i * 128;
        out[(size_t)t * D_DIM + c] = (v[i] - mean) * rstd * gamma[c] + beta[c];
    }
}

// ---------------------------------------------------------------------------
extern "C" void kernel_launch(void* const* d_in, const int* in_sizes, int n_in,
                              void* d_out, int out_size) {
    const float* x     = (const float*)d_in[0];
    const float* W1    = (const float*)d_in[1];
    const float* b1    = (const float*)d_in[2];
    const float* W2    = (const float*)d_in[3];
    const float* b2    = (const float*)d_in[4];
    const float* gamma = (const float*)d_in[5];
    const float* beta  = (const float*)d_in[6];
    const int*   orig  = (const int*)d_in[7];
    const int*   hmap  = (const int*)d_in[8];
    float* out = (float*)d_out;

    setup_kernel<<<1, 256>>>(orig, hmap);
    gemm1_kernel<<<dim3(MAX_TILES, H_DIM / BN), 256>>>(x, W1, b1);
    gemm2_kernel<<<dim3(MAX_TILES, D_DIM / BN), 256>>>(W2, b2);
    ln_kernel<<<T_TOK, 128>>>(x, gamma, beta, out);
}

// round 2
// speedup vs baseline: 1.4316x; 1.4316x over previous
#include <cuda_runtime.h>
#include <cuda_bf16.h>
#include <cstdint>
#include <cstddef>

// Problem constants
#define T_TOK 2048
#define D_DIM 512
#define H_DIM 2048
#define N_EXP 8
#define BM 128
#define BN 128
#define BK 32
#define PAD_ROWS 3072
#define MAX_TILES 24
#define AS_STRIDE 36          // 32 + 4 pad (words); row stride 144B (16B aligned)
#define BS_STRIDE 136         // 128 + 8 pad (words); row stride 544B (16B aligned)
#define STAGE_WORDS (BM * AS_STRIDE + BK * BS_STRIDE)   // 4608 + 4352 = 8960
#define SMEM_BYTES (2 * STAGE_WORDS * 4)                // 71680

// Scratch (allocation-free rule: device globals)
__device__ int   g_perm[PAD_ROWS];
__device__ int   g_tile_expert[MAX_TILES + 8];
__device__ float g_h[(size_t)PAD_ROWS * H_DIM];
__device__ float g_ffn[2][(size_t)T_TOK * D_DIM];   // split-K partials

__device__ __forceinline__ void cp16(uint32_t dst, const void* src, bool pred) {
    int sz = pred ? 16 : 0;
    asm volatile("cp.async.cg.shared.global [%0], [%1], 16, %2;\n"
                 :: "r"(dst), "l"(src), "r"(sz));
}
__device__ __forceinline__ void cp_commit() { asm volatile("cp.async.commit_group;\n"); }
__device__ __forceinline__ void cp_wait0()  { asm volatile("cp.async.wait_group 0;\n"); }

__device__ __forceinline__ void mma8(float* c,
                                     uint32_t a0, uint32_t a1, uint32_t a2, uint32_t a3,
                                     uint32_t b0, uint32_t b1) {
    asm volatile(
        "mma.sync.aligned.m16n8k8.row.col.f32.tf32.tf32.f32 "
        "{%0,%1,%2,%3}, {%4,%5,%6,%7}, {%8,%9}, {%0,%1,%2,%3};\n"
        : "+f"(c[0]), "+f"(c[1]), "+f"(c[2]), "+f"(c[3])
        : "r"(a0), "r"(a1), "r"(a2), "r"(a3), "r"(b0), "r"(b1));
}

// ---------------------------------------------------------------------------
// Setup: bins -> histogram -> padded grouped permutation + tile expert table
// ---------------------------------------------------------------------------
__global__ void setup_kernel(const int* __restrict__ orig, const int* __restrict__ hmap) {
    __shared__ int cnt[N_EXP];
    __shared__ int padoff[N_EXP];
    __shared__ int scat[N_EXP];
    int tid = threadIdx.x;

    if (tid < N_EXP) cnt[tid] = 0;
    __syncthreads();

    for (int t = tid; t < T_TOK; t += 256) {
        int b = hmap[orig[t]];
        atomicAdd(&cnt[b], 1);
    }
    for (int i = tid; i < PAD_ROWS; i += 256) g_perm[i] = -1;
    if (tid < MAX_TILES + 8) g_tile_expert[tid] = -1;
    __syncthreads();

    if (tid == 0) {
        int tile = 0;
        for (int e = 0; e < N_EXP; e++) {
            padoff[e] = tile * BM;
            scat[e] = 0;
            int nt = (cnt[e] + BM - 1) / BM;
            for (int i = 0; i < nt; i++) g_tile_expert[tile++] = e;
        }
    }
    __syncthreads();

    for (int t = tid; t < T_TOK; t += 256) {
        int b = hmap[orig[t]];
        int r = atomicAdd(&scat[b], 1);
        g_perm[padoff[b] + r] = t;
    }
}

// ---------------------------------------------------------------------------
// Shared warp-level compute on one (As, Bs) stage
// ---------------------------------------------------------------------------
__device__ __forceinline__ void compute_stage(const uint32_t* As, const uint32_t* Bs,
                                              float acc[4][4][4],
                                              int wm, int wn, int gid, int tig) {
#pragma unroll
    for (int ks = 0; ks < 4; ++ks) {
        int k0 = ks * 8;
        uint32_t af[4][4], bf[4][2];
#pragma unroll
        for (int mi = 0; mi < 4; ++mi) {
            int r0 = wm * 64 + mi * 16 + gid;
            af[mi][0] = As[r0 * AS_STRIDE + k0 + tig];
            af[mi][1] = As[(r0 + 8) * AS_STRIDE + k0 + tig];
            af[mi][2] = As[r0 * AS_STRIDE + k0 + tig + 4];
            af[mi][3] = As[(r0 + 8) * AS_STRIDE + k0 + tig + 4];
        }
#pragma unroll
        for (int ni = 0; ni < 4; ++ni) {
            int cb = wn * 32 + ni * 8 + gid;
            bf[ni][0] = Bs[(k0 + tig) * BS_STRIDE + cb];
            bf[ni][1] = Bs[(k0 + tig + 4) * BS_STRIDE + cb];
        }
#pragma unroll
        for (int mi = 0; mi < 4; ++mi)
#pragma unroll
            for (int ni = 0; ni < 4; ++ni)
                mma8(acc[mi][ni], af[mi][0], af[mi][1], af[mi][2], af[mi][3],
                     bf[ni][0], bf[ni][1]);
    }
}

// ---------------------------------------------------------------------------
// GEMM1: h = relu(x[perm] @ W1[e] + b1[e]); cp.async double-buffered
// grid = (MAX_TILES, H/128), 256 threads
// ---------------------------------------------------------------------------
__global__ __launch_bounds__(256, 2) void gemm1_kernel(const float* __restrict__ x,
                                                       const float* __restrict__ W1,
                                                       const float* __restrict__ b1) {
    int te = g_tile_expert[blockIdx.x];
    if (te < 0) return;

    extern __shared__ uint32_t smx[];
    __shared__ int toks[BM];

    int tid = threadIdx.x;
    if (tid < BM) toks[tid] = g_perm[blockIdx.x * BM + tid];
    __syncthreads();

    const float* We = W1 + (size_t)te * D_DIM * H_DIM;
    int nbase = blockIdx.y * BN;
    int lane = tid & 31, wid = tid >> 5;
    int wm = wid & 1, wn = wid >> 1;
    int gid = lane >> 2, tig = lane & 3;

    uint32_t sbase = (uint32_t)__cvta_generic_to_shared(smx);

    // A load mapping: 1024 float4 slots; l = tid + 256*j -> row = (tid>>3)+32j, col4 = tid&7
    int la_r = tid >> 3, la_c = (tid & 7) * 4;
    int lb_r = tid >> 5, lb_c = (tid & 31) * 4;

    const float* arow[4]; bool aval[4];
#pragma unroll
    for (int j = 0; j < 4; ++j) {
        int tk = toks[la_r + 32 * j];
        aval[j] = (tk >= 0);
        arow[j] = x + (size_t)(tk >= 0 ? tk : 0) * D_DIM + la_c;
    }

    float acc[4][4][4];
#pragma unroll
    for (int i = 0; i < 4; i++)
#pragma unroll
        for (int j = 0; j < 4; j++)
#pragma unroll
            for (int k = 0; k < 4; k++) acc[i][j][k] = 0.f;

    const int KB = D_DIM / BK;   // 16

    auto issue = [&](int kb, int s) {
        uint32_t abase = sbase + (uint32_t)s * STAGE_WORDS * 4;
#pragma unroll
        for (int j = 0; j < 4; ++j)
            cp16(abase + ((la_r + 32 * j) * AS_STRIDE + la_c) * 4,
                 arow[j] + kb * BK, aval[j]);
        uint32_t bbase = abase + BM * AS_STRIDE * 4;
#pragma unroll
        for (int j = 0; j < 4; ++j)
            cp16(bbase + ((lb_r + 8 * j) * BS_STRIDE + lb_c) * 4,
                 We + (size_t)(kb * BK + lb_r + 8 * j) * H_DIM + nbase + lb_c, true);
        cp_commit();
    };

    issue(0, 0);
    for (int kb = 0; kb < KB; ++kb) {
        cp_wait0();
        __syncthreads();
        if (kb + 1 < KB) issue(kb + 1, (kb + 1) & 1);
        const uint32_t* As = smx + (kb & 1) * STAGE_WORDS;
        const uint32_t* Bs = As + BM * AS_STRIDE;
        compute_stage(As, Bs, acc, wm, wn, gid, tig);
    }

    const float* be = b1 + (size_t)te * H_DIM;
    int rowbase = blockIdx.x * BM;
#pragma unroll
    for (int ni = 0; ni < 4; ++ni) {
        int c0 = nbase + wn * 32 + ni * 8 + tig * 2;
        float bb0 = be[c0], bb1 = be[c0 + 1];
#pragma unroll
        for (int mi = 0; mi < 4; ++mi) {
            int r0 = rowbase + wm * 64 + mi * 16 + gid;
            float2 v0, v1;
            v0.x = fmaxf(acc[mi][ni][0] + bb0, 0.f);
            v0.y = fmaxf(acc[mi][ni][1] + bb1, 0.f);
            v1.x = fmaxf(acc[mi][ni][2] + bb0, 0.f);
            v1.y = fmaxf(acc[mi][ni][3] + bb1, 0.f);
            *(float2*)(g_h + (size_t)r0 * H_DIM + c0) = v0;
            *(float2*)(g_h + (size_t)(r0 + 8) * H_DIM + c0) = v1;
        }
    }
}

// ---------------------------------------------------------------------------
// GEMM2: y_part = h @ W2[e] (K split in 2) + b2 (split 0 only); scatter
// grid = (MAX_TILES, D/128, 2), 256 threads
// ---------------------------------------------------------------------------
__global__ __launch_bounds__(256, 2) void gemm2_kernel(const float* __restrict__ W2,
                                                       const float* __restrict__ b2) {
    int te = g_tile_expert[blockIdx.x];
    if (te < 0) return;

    extern __shared__ uint32_t smx[];
    __shared__ int toks[BM];

    int tid = threadIdx.x;
    if (tid < BM) toks[tid] = g_perm[blockIdx.x * BM + tid];
    __syncthreads();

    const float* We = W2 + (size_t)te * H_DIM * D_DIM;
    const float* Ae = g_h + (size_t)blockIdx.x * BM * H_DIM;
    int nbase = blockIdx.y * BN;
    int split = blockIdx.z;
    int lane = tid & 31, wid = tid >> 5;
    int wm = wid & 1, wn = wid >> 1;
    int gid = lane >> 2, tig = lane & 3;

    uint32_t sbase = (uint32_t)__cvta_generic_to_shared(smx);
    int la_r = tid >> 3, la_c = (tid & 7) * 4;
    int lb_r = tid >> 5, lb_c = (tid & 31) * 4;

    float acc[4][4][4];
#pragma unroll
    for (int i = 0; i < 4; i++)
#pragma unroll
        for (int j = 0; j < 4; j++)
#pragma unroll
            for (int k = 0; k < 4; k++) acc[i][j][k] = 0.f;

    const int KB = (H_DIM / 2) / BK;     // 32
    const int kb0 = split * KB;

    auto issue = [&](int kb, int s) {
        uint32_t abase = sbase + (uint32_t)s * STAGE_WORDS * 4;
#pragma unroll
        for (int j = 0; j < 4; ++j)
            cp16(abase + ((la_r + 32 * j) * AS_STRIDE + la_c) * 4,
                 Ae + (size_t)(la_r + 32 * j) * H_DIM + (kb0 + kb) * BK + la_c, true);
        uint32_t bbase = abase + BM * AS_STRIDE * 4;
#pragma unroll
        for (int j = 0; j < 4; ++j)
            cp16(bbase + ((lb_r + 8 * j) * BS_STRIDE + lb_c) * 4,
                 We + (size_t)((kb0 + kb) * BK + lb_r + 8 * j) * D_DIM + nbase + lb_c, true);
        cp_commit();
    };

    issue(0, 0);
    for (int kb = 0; kb < KB; ++kb) {
        cp_wait0();
        __syncthreads();
        if (kb + 1 < KB) issue(kb + 1, (kb + 1) & 1);
        const uint32_t* As = smx + (kb & 1) * STAGE_WORDS;
        const uint32_t* Bs = As + BM * AS_STRIDE;
        compute_stage(As, Bs, acc, wm, wn, gid, tig);
    }

    const float* be = b2 + (size_t)te * D_DIM;
    float* dst = g_ffn[split];
#pragma unroll
    for (int ni = 0; ni < 4; ++ni) {
        int c0 = nbase + wn * 32 + ni * 8 + tig * 2;
        float bb0 = split == 0 ? be[c0] : 0.f;
        float bb1 = split == 0 ? be[c0 + 1] : 0.f;
#pragma unroll
        for (int mi = 0; mi < 4; ++mi) {
            int rl0 = wm * 64 + mi * 16 + gid;
            int tk0 = toks[rl0];
            int tk1 = toks[rl0 + 8];
            if (tk0 >= 0) {
                float2 v;
                v.x = acc[mi][ni][0] + bb0;
                v.y = acc[mi][ni][1] + bb1;
                *(float2*)(dst + (size_t)tk0 * D_DIM + c0) = v;
            }
            if (tk1 >= 0) {
                float2 v;
                v.x = acc[mi][ni][2] + bb0;
                v.y = acc[mi][ni][3] + bb1;
                *(float2*)(dst + (size_t)tk1 * D_DIM + c0) = v;
            }
        }
    }
}

// ---------------------------------------------------------------------------
// Residual + LayerNorm (sums the two split-K partials), float4 vectorized
// ---------------------------------------------------------------------------
__global__ void ln_kernel(const float* __restrict__ x,
                          const float* __restrict__ gamma,
                          const float* __restrict__ beta,
                          float* __restrict__ out) {
    int t = blockIdx.x;
    int tid = threadIdx.x;  // 128
    size_t off = (size_t)t * D_DIM + tid * 4;

    float4 xv = *(const float4*)(x + off);
    float4 f0 = *(const float4*)(g_ffn[0] + off);
    float4 f1 = *(const float4*)(g_ffn[1] + off);
    float4 z;
    z.x = xv.x + f0.x + f1.x;
    z.y = xv.y + f0.y + f1.y;
    z.z = xv.z + f0.z + f1.z;
    z.w = xv.w + f0.w + f1.w;

    float s = z.x + z.y + z.z + z.w;
    float ss = z.x * z.x + z.y * z.y + z.z * z.z + z.w * z.w;
#pragma unroll
    for (int o = 16; o > 0; o >>= 1) {
        s += __shfl_xor_sync(0xffffffffu, s, o);
        ss += __shfl_xor_sync(0xffffffffu, ss, o);
    }
    __shared__ float sm[8];
    int w = tid >> 5;
    if ((tid & 31) == 0) { sm[w] = s; sm[4 + w] = ss; }
    __syncthreads();
    s = sm[0] + sm[1] + sm[2] + sm[3];
    ss = sm[4] + sm[5] + sm[6] + sm[7];

    float mean = s * (1.f / 512.f);
    float var = ss * (1.f / 512.f) - mean * mean;
    float rstd = rsqrtf(var + 1e-5f);

    float4 gv = *(const float4*)(gamma + tid * 4);
    float4 bv = *(const float4*)(beta + tid * 4);
    float4 o4;
    o4.x = (z.x - mean) * rstd * gv.x + bv.x;
    o4.y = (z.y - mean) * rstd * gv.y + bv.y;
    o4.z = (z.z - mean) * rstd * gv.z + bv.z;
    o4.w = (z.w - mean) * rstd * gv.w + bv.w;
    *(float4*)(out + off) = o4;
}

// ---------------------------------------------------------------------------
extern "C" void kernel_launch(void* const* d_in, const int* in_sizes, int n_in,
                              void* d_out, int out_size) {
    const float* x     = (const float*)d_in[0];
    const float* W1    = (const float*)d_in[1];
    const float* b1    = (const float*)d_in[2];
    const float* W2    = (const float*)d_in[3];
    const float* b2    = (const float*)d_in[4];
    const float* gamma = (const float*)d_in[5];
    const float* beta  = (const float*)d_in[6];
    const int*   orig  = (const int*)d_in[7];
    const int*   hmap  = (const int*)d_in[8];
    float* out = (float*)d_out;

    cudaFuncSetAttribute(gemm1_kernel, cudaFuncAttributeMaxDynamicSharedMemorySize, SMEM_BYTES);
    cudaFuncSetAttribute(gemm2_kernel, cudaFuncAttributeMaxDynamicSharedMemorySize, SMEM_BYTES);

    setup_kernel<<<1, 256>>>(orig, hmap);
    gemm1_kernel<<<dim3(MAX_TILES, H_DIM / BN), 256, SMEM_BYTES>>>(x, W1, b1);
    gemm2_kernel<<<dim3(MAX_TILES, D_DIM / BN, 2), 256, SMEM_BYTES>>>(W2, b2);
    ln_kernel<<<T_TOK, 128>>>(x, gamma, beta, out);
}

// round 5
// speedup vs baseline: 1.7617x; 1.2306x over previous
#include <cuda_runtime.h>
#include <cuda_bf16.h>
#include <cstdint>
#include <cstddef>

// Problem constants
#define T_TOK 2048
#define D_DIM 512
#define H_DIM 2048
#define N_EXP 8
#define BM 128
#define BN 256
#define BK 32
#define PAD_ROWS 3072
#define MAX_TILES 24
#define AS_STRIDE 36            // 32 + 4 pad words (144 B rows, 16B aligned)
#define BS_STRIDE 264           // 256 + 8 pad words (1056 B rows, 16B aligned)
#define STAGE_WORDS (BM * AS_STRIDE + BK * BS_STRIDE)   // 4608 + 8448 = 13056
#define STAGES 3
#define SMEM_BYTES (STAGES * STAGE_WORDS * 4)           // 156672

// GEMM2 split-K over 64 chunks: 22/21/21
#define G2_CHUNKS 64
#define NSPLIT 3

// Scratch (device globals: allocation-free rule)
__device__ int   g_perm[PAD_ROWS];
__device__ int   g_tile_expert[MAX_TILES + 8];
__device__ float g_h[(size_t)PAD_ROWS * H_DIM];
__device__ float g_ffn[NSPLIT][(size_t)T_TOK * D_DIM];

__device__ __forceinline__ void cp16(uint32_t dst, const void* src, bool pred) {
    int sz = pred ? 16 : 0;
    asm volatile("cp.async.cg.shared.global [%0], [%1], 16, %2;\n"
                 :: "r"(dst), "l"(src), "r"(sz));
}
__device__ __forceinline__ void cp_commit() { asm volatile("cp.async.commit_group;\n"); }
template <int N> __device__ __forceinline__ void cp_wait() {
    asm volatile("cp.async.wait_group %0;\n" :: "n"(N));
}

__device__ __forceinline__ void mma8(float* c,
                                     uint32_t a0, uint32_t a1, uint32_t a2, uint32_t a3,
                                     uint32_t b0, uint32_t b1) {
    asm volatile(
        "mma.sync.aligned.m16n8k8.row.col.f32.tf32.tf32.f32 "
        "{%0,%1,%2,%3}, {%4,%5,%6,%7}, {%8,%9}, {%0,%1,%2,%3};\n"
        : "+f"(c[0]), "+f"(c[1]), "+f"(c[2]), "+f"(c[3])
        : "r"(a0), "r"(a1), "r"(a2), "r"(a3), "r"(b0), "r"(b1));
}

// ---------------------------------------------------------------------------
// Setup: bins -> histogram -> padded grouped permutation + tile expert table
// ---------------------------------------------------------------------------
__global__ void setup_kernel(const int* __restrict__ orig, const int* __restrict__ hmap) {
    __shared__ int cnt[N_EXP];
    __shared__ int padoff[N_EXP];
    __shared__ int scat[N_EXP];
    int tid = threadIdx.x;

    if (tid < N_EXP) cnt[tid] = 0;
    __syncthreads();

    for (int t = tid; t < T_TOK; t += 256) {
        int b = hmap[orig[t]];
        atomicAdd(&cnt[b], 1);
    }
    for (int i = tid; i < PAD_ROWS; i += 256) g_perm[i] = -1;
    if (tid < MAX_TILES + 8) g_tile_expert[tid] = -1;
    __syncthreads();

    if (tid == 0) {
        int tile = 0;
        for (int e = 0; e < N_EXP; e++) {
            padoff[e] = tile * BM;
            scat[e] = 0;
            int nt = (cnt[e] + BM - 1) / BM;
            for (int i = 0; i < nt; i++) g_tile_expert[tile++] = e;
        }
    }
    __syncthreads();

    for (int t = tid; t < T_TOK; t += 256) {
        int b = hmap[orig[t]];
        int r = atomicAdd(&scat[b], 1);
        g_perm[padoff[b] + r] = t;
    }
}

// ---------------------------------------------------------------------------
// Warp compute on one stage: warp tile 64x64, 4 ks steps of k8
// ---------------------------------------------------------------------------
__device__ __forceinline__ void compute_stage(const uint32_t* As, const uint32_t* Bs,
                                              float acc[4][8][4],
                                              int wm, int wn, int gid, int tig) {
#pragma unroll
    for (int ks = 0; ks < 4; ++ks) {
        int k0 = ks * 8;
        uint32_t af[4][4], bf[8][2];
#pragma unroll
        for (int mi = 0; mi < 4; ++mi) {
            int r0 = wm * 64 + mi * 16 + gid;
            af[mi][0] = As[r0 * AS_STRIDE + k0 + tig];
            af[mi][1] = As[(r0 + 8) * AS_STRIDE + k0 + tig];
            af[mi][2] = As[r0 * AS_STRIDE + k0 + tig + 4];
            af[mi][3] = As[(r0 + 8) * AS_STRIDE + k0 + tig + 4];
        }
#pragma unroll
        for (int ni = 0; ni < 8; ++ni) {
            int cb = wn * 64 + ni * 8 + gid;
            bf[ni][0] = Bs[(k0 + tig) * BS_STRIDE + cb];
            bf[ni][1] = Bs[(k0 + tig + 4) * BS_STRIDE + cb];
        }
#pragma unroll
        for (int mi = 0; mi < 4; ++mi)
#pragma unroll
            for (int ni = 0; ni < 8; ++ni)
                mma8(acc[mi][ni], af[mi][0], af[mi][1], af[mi][2], af[mi][3],
                     bf[ni][0], bf[ni][1]);
    }
}

// ---------------------------------------------------------------------------
// Unified GEMM (tf32 mma.sync, 128x256 CTA tile, 3-stage cp.async)
//   G1: h = relu(x[perm] @ W1[e] + b1[e])    grid (tiles, H/256)
//   G2: g_ffn[z] = h @ W2[e][ksplit] (+b2)   grid (tiles, D/256, 3)
// ---------------------------------------------------------------------------
template <bool G1>
__global__ __launch_bounds__(256, 1) void gemm_kernel(const float* __restrict__ Aglob,
                                                      const float* __restrict__ W,
                                                      const float* __restrict__ bias) {
    int te = g_tile_expert[blockIdx.x];
    if (te < 0) return;

    extern __shared__ uint32_t smx[];
    __shared__ int toks[BM];

    const int tid = threadIdx.x;
    if (tid < BM) toks[tid] = g_perm[blockIdx.x * BM + tid];
    __syncthreads();

    const int ldn = G1 ? H_DIM : D_DIM;
    const int split = G1 ? 0 : blockIdx.z;
    const int nbase = blockIdx.y * BN;
    const int lane = tid & 31, wid = tid >> 5;
    const int wm = wid & 1, wn = wid >> 1;
    const int gid = lane >> 2, tig = lane & 3;

    // chunk range
    int cb0, ncb;
    if (G1) { cb0 = 0; ncb = D_DIM / BK; }                 // 16
    else {
        int base = (G2_CHUNKS / NSPLIT);                    // 21
        int extra = G2_CHUNKS - base * NSPLIT;              // 1
        cb0 = split * base + (split < extra ? split : extra);
        ncb = base + (split < extra ? 1 : 0);               // 22/21/21
    }

    const float* We = W + (size_t)te * (size_t)D_DIM * H_DIM;   // same size both ways

    uint32_t sbase = (uint32_t)__cvta_generic_to_shared(smx);

    // A loads: 1024 cp16/chunk -> 4/thread; id = tid + 256j: r=id/8, c4=id%8
    const int a_r = tid >> 3, a_c4 = (tid & 7) * 4;
    const float* a_src[4]; bool a_val[4];
#pragma unroll
    for (int j = 0; j < 4; ++j) {
        int r = a_r + 32 * j;
        if (G1) {
            int tk = toks[r];
            a_val[j] = (tk >= 0);
            a_src[j] = Aglob + (size_t)(tk >= 0 ? tk : 0) * D_DIM + a_c4;
        } else {
            a_val[j] = true;
            a_src[j] = g_h + ((size_t)blockIdx.x * BM + r) * H_DIM + a_c4;
        }
    }
    // B loads: 2048 cp16/chunk -> 8/thread; id = tid + 256j: kr=id/64, n4=id%64
    const int b_kr = tid >> 6, b_n4 = (tid & 63) * 4;

    float acc[4][8][4];
#pragma unroll
    for (int i = 0; i < 4; i++)
#pragma unroll
        for (int j = 0; j < 8; j++)
#pragma unroll
            for (int k = 0; k < 4; k++) acc[i][j][k] = 0.f;

    auto issue = [&](int c) {   // c = local chunk index
        int kb = cb0 + c;
        uint32_t st = sbase + (uint32_t)(c % STAGES) * STAGE_WORDS * 4;
#pragma unroll
        for (int j = 0; j < 4; ++j)
            cp16(st + ((a_r + 32 * j) * AS_STRIDE + a_c4) * 4,
                 a_src[j] + kb * BK, a_val[j]);
        uint32_t bb = st + BM * AS_STRIDE * 4;
#pragma unroll
        for (int j = 0; j < 8; ++j) {
            int kr = b_kr + 4 * j;
            cp16(bb + (kr * BS_STRIDE + b_n4) * 4,
                 We + (size_t)(kb * BK + kr) * ldn + nbase + b_n4, true);
        }
        cp_commit();
    };

    issue(0);
    issue(1);
    for (int c = 0; c < ncb; ++c) {
        cp_wait<STAGES - 2>();
        __syncthreads();
        if (c + STAGES - 1 < ncb) issue(c + STAGES - 1);
        const uint32_t* As = smx + (c % STAGES) * STAGE_WORDS;
        const uint32_t* Bs = As + BM * AS_STRIDE;
        compute_stage(As, Bs, acc, wm, wn, gid, tig);
        __syncthreads();
    }

    // ---- epilogue ----
    const float* be = bias + (size_t)te * (G1 ? H_DIM : D_DIM);
    if (G1) {
        int rowbase = blockIdx.x * BM;
#pragma unroll
        for (int ni = 0; ni < 8; ++ni) {
            int c0 = nbase + wn * 64 + ni * 8 + tig * 2;
            float bb0 = be[c0], bb1 = be[c0 + 1];
#pragma unroll
            for (int mi = 0; mi < 4; ++mi) {
                int r0 = rowbase + wm * 64 + mi * 16 + gid;
                float2 v0, v1;
                v0.x = fmaxf(acc[mi][ni][0] + bb0, 0.f);
                v0.y = fmaxf(acc[mi][ni][1] + bb1, 0.f);
                v1.x = fmaxf(acc[mi][ni][2] + bb0, 0.f);
                v1.y = fmaxf(acc[mi][ni][3] + bb1, 0.f);
                *(float2*)(g_h + (size_t)r0 * H_DIM + c0) = v0;
                *(float2*)(g_h + (size_t)(r0 + 8) * H_DIM + c0) = v1;
            }
        }
    } else {
        float* dst = g_ffn[split];
#pragma unroll
        for (int ni = 0; ni < 8; ++ni) {
            int c0 = nbase + wn * 64 + ni * 8 + tig * 2;
            float bb0 = split == 0 ? be[c0] : 0.f;
            float bb1 = split == 0 ? be[c0 + 1] : 0.f;
#pragma unroll
            for (int mi = 0; mi < 4; ++mi) {
                int rl0 = wm * 64 + mi * 16 + gid;
                int tk0 = toks[rl0];
                int tk1 = toks[rl0 + 8];
                if (tk0 >= 0) {
                    float2 v;
                    v.x = acc[mi][ni][0] + bb0;
                    v.y = acc[mi][ni][1] + bb1;
                    *(float2*)(dst + (size_t)tk0 * D_DIM + c0) = v;
                }
                if (tk1 >= 0) {
                    float2 v;
                    v.x = acc[mi][ni][2] + bb0;
                    v.y = acc[mi][ni][3] + bb1;
                    *(float2*)(dst + (size_t)tk1 * D_DIM + c0) = v;
                }
            }
        }
    }
}

// ---------------------------------------------------------------------------
// Residual + LayerNorm (sums the three split-K partials)
// ---------------------------------------------------------------------------
__global__ void ln_kernel(const float* __restrict__ x,
                          const float* __restrict__ gamma,
                          const float* __restrict__ beta,
                          float* __restrict__ out) {
    int t = blockIdx.x;
    int tid = threadIdx.x;  // 128
    size_t off = (size_t)t * D_DIM + tid * 4;

    float4 xv = *(const float4*)(x + off);
    float4 f0 = *(const float4*)(g_ffn[0] + off);
    float4 f1 = *(const float4*)(g_ffn[1] + off);
    float4 f2 = *(const float4*)(g_ffn[2] + off);
    float4 z;
    z.x = xv.x + f0.x + f1.x + f2.x;
    z.y = xv.y + f0.y + f1.y + f2.y;
    z.z = xv.z + f0.z + f1.z + f2.z;
    z.w = xv.w + f0.w + f1.w + f2.w;

    float s = z.x + z.y + z.z + z.w;
    float ss = z.x * z.x + z.y * z.y + z.z * z.z + z.w * z.w;
#pragma unroll
    for (int o = 16; o > 0; o >>= 1) {
        s += __shfl_xor_sync(0xffffffffu, s, o);
        ss += __shfl_xor_sync(0xffffffffu, ss, o);
    }
    __shared__ float sm[8];
    int w = tid >> 5;
    if ((tid & 31) == 0) { sm[w] = s; sm[4 + w] = ss; }
    __syncthreads();
    s = sm[0] + sm[1] + sm[2] + sm[3];
    ss = sm[4] + sm[5] + sm[6] + sm[7];

    float mean = s * (1.f / 512.f);
    float var = ss * (1.f / 512.f) - mean * mean;
    float rstd = rsqrtf(var + 1e-5f);

    float4 gv = *(const float4*)(gamma + tid * 4);
    float4 bv = *(const float4*)(beta + tid * 4);
    float4 o4;
    o4.x = (z.x - mean) * rstd * gv.x + bv.x;
    o4.y = (z.y - mean) * rstd * gv.y + bv.y;
    o4.z = (z.z - mean) * rstd * gv.z + bv.z;
    o4.w = (z.w - mean) * rstd * gv.w + bv.w;
    *(float4*)(out + off) = o4;
}

// ---------------------------------------------------------------------------
extern "C" void kernel_launch(void* const* d_in, const int* in_sizes, int n_in,
                              void* d_out, int out_size) {
    const float* x     = (const float*)d_in[0];
    const float* W1    = (const float*)d_in[1];
    const float* b1    = (const float*)d_in[2];
    const float* W2    = (const float*)d_in[3];
    const float* b2    = (const float*)d_in[4];
    const float* gamma = (const float*)d_in[5];
    const float* beta  = (const float*)d_in[6];
    const int*   orig  = (const int*)d_in[7];
    const int*   hmap  = (const int*)d_in[8];
    float* out = (float*)d_out;

    cudaFuncSetAttribute(gemm_kernel<true>, cudaFuncAttributeMaxDynamicSharedMemorySize, SMEM_BYTES);
    cudaFuncSetAttribute(gemm_kernel<false>, cudaFuncAttributeMaxDynamicSharedMemorySize, SMEM_BYTES);

    setup_kernel<<<1, 256>>>(orig, hmap);
    gemm_kernel<true><<<dim3(MAX_TILES, H_DIM / BN), 256, SMEM_BYTES>>>(x, W1, b1);
    gemm_kernel<false><<<dim3(MAX_TILES, D_DIM / BN, NSPLIT), 256, SMEM_BYTES>>>(nullptr, W2, b2);
    ln_kernel<<<T_TOK, 128>>>(x, gamma, beta, out);
}